// round 17
// baseline (speedup 1.0000x reference)
#include <cuda_runtime.h>
#include <math.h>
#include <stdint.h>

// Problem constants
#define B_   32
#define IU_  16
#define IC_  2048
#define NU_  16
#define US_  64
#define ICH  64            // chunks over i
#define CH   (IC_/ICH)     // 32 i per chunk

// Scratch (device globals: allocation-free)
__device__ uint32_t g_Apk[(size_t)IC_ * 4 * 32 * 4];           // 4 MB, tf32 bits, mma A-frag order
__device__ float    g_part[(size_t)ICH * B_ * NU_ * US_];      // 8 MB [chunk][b][j][k]

// ---------------------------------------------------------------------------
__device__ __forceinline__ uint32_t f2tf(float f) {
    uint32_t r;
    asm("cvt.rna.tf32.f32 %0, %1;" : "=r"(r) : "f"(f));
    return r;
}

// ---------------------------------------------------------------------------
// Kernel 1: repack x[b][u][i] -> mma A-fragment order (tf32 bits).
// ONE-WAVE design: grid (64, 2) = 128 blocks <= 148 SMs. Each block handles a
// 32-i slab; ALL 8 LDG.128/thread are issued up front (MLP=8), one barrier,
// then 8 STG.128/thread. No wave transitions (the cost that dominated all
// previous prep variants).
// ---------------------------------------------------------------------------
__global__ void __launch_bounds__(256, 2) prep_kernel(const float* __restrict__ x) {
    __shared__ float xs[4][256][9];           // [step][local row][i_local 0..7]
    const int i_base = blockIdx.x * 32;
    const int mt     = blockIdx.y;            // b-half
    const int tid    = threadIdx.x;

    // front-batched loads: 4 steps x 2 float4/thread = 8 independent LDGs
    float4 r[8];
    #pragma unroll
    for (int st = 0; st < 4; ++st) {
        #pragma unroll
        for (int p = 0; p < 2; ++p) {
            int q  = tid + p * 256;
            int rl = q >> 1;                  // local row 0..255
            int f  = q & 1;
            r[st * 2 + p] = *(const float4*)(
                x + (size_t)(mt * 256 + rl) * IC_ + i_base + st * 8 + f * 4);
        }
    }
    #pragma unroll
    for (int st = 0; st < 4; ++st) {
        #pragma unroll
        for (int p = 0; p < 2; ++p) {
            int q  = tid + p * 256;
            int rl = q >> 1;
            int f  = q & 1;
            float4 v = r[st * 2 + p];
            xs[st][rl][f*4+0] = v.x; xs[st][rl][f*4+1] = v.y;
            xs[st][rl][f*4+2] = v.z; xs[st][rl][f*4+3] = v.w;
        }
    }
    __syncthreads();

    // phase 2: 4 steps x 2 uint4/thread, coalesced stores
    #pragma unroll
    for (int st = 0; st < 4; ++st) {
        #pragma unroll
        for (int p = 0; p < 2; ++p) {
            int q    = tid + p * 256;
            int lane = q & 31;
            int t    = (q >> 5) & 1;
            int il   = q >> 6;                // 0..7
            int slot = 2 * t + mt;
            int u0   = 4 * (lane & 3) + 2 * t;
            int r00  = (lane >> 2) * 16 + u0;
            uint4 v;
            v.x = f2tf(xs[st][r00      ][il]);
            v.y = f2tf(xs[st][r00 + 128][il]);    // b0+8
            v.z = f2tf(xs[st][r00 +   1][il]);    // u0+1
            v.w = f2tf(xs[st][r00 + 129][il]);
            *(uint4*)(g_Apk +
                (((size_t)(i_base + st * 8 + il) * 4 + slot) * 32 + lane) * 4) = v;
        }
    }
}

// ---------------------------------------------------------------------------
__device__ __forceinline__ void mma_tf32(float c[4], uint4 a,
                                         uint32_t b0, uint32_t b1) {
    asm volatile(
        "mma.sync.aligned.m16n8k8.row.col.f32.tf32.tf32.f32 "
        "{%0,%1,%2,%3}, {%4,%5,%6,%7}, {%8,%9}, {%0,%1,%2,%3};"
        : "+f"(c[0]), "+f"(c[1]), "+f"(c[2]), "+f"(c[3])
        : "r"(a.x), "r"(a.y), "r"(a.z), "r"(a.w), "r"(b0), "r"(b1));
}

__device__ __forceinline__ float4 ldcs4(const float4* p) {
    float4 v;
    asm volatile("ld.global.cs.v4.f32 {%0,%1,%2,%3}, [%4];"
                 : "=f"(v.x), "=f"(v.y), "=f"(v.z), "=f"(v.w) : "l"(p));
    return v;
}

// ---------------------------------------------------------------------------
// Kernel 2: tf32 GEMM partials, j-fan-out 4, register pipeline.
// B-side cvt REMOVED: tf32 mma ignores the low 13 mantissa bits of operand
// registers, so raw fp32 W bits are fed directly (truncation vs rna — small
// accuracy cost, ~30% fewer non-mma instructions in the hot loop).
// ---------------------------------------------------------------------------
__global__ void __launch_bounds__(256, 2) gemm_kernel(const float* __restrict__ W) {
    const int j0    = blockIdx.y * 4;
    const int chunk = blockIdx.x;
    const int i0    = chunk * CH;
    const int warp  = threadIdx.x >> 5;
    const int lane  = threadIdx.x & 31;
    const int kc0   = warp * 8;

    float c0[4][4], c1[4][4];
    #pragma unroll
    for (int d = 0; d < 4; ++d)
        #pragma unroll
        for (int r = 0; r < 4; ++r) { c0[d][r] = 0.f; c1[d][r] = 0.f; }

    const float4* __restrict__ bp =
        (const float4*)(W + (((size_t)i0 * NU_ + j0) * US_ + kc0) * IU_) + lane;
    const uint4* __restrict__ ap =
        (const uint4*)(g_Apk) + (size_t)i0 * 128 + lane;

    // W pipeline depth 2: w[j][buf]
    float4 w[4][2];
    #pragma unroll
    for (int s = 0; s < 2; ++s)
        #pragma unroll
        for (int d = 0; d < 4; ++d)
            w[d][s] = ldcs4(bp + (size_t)s * 4096 + d * 256);

    // A depth-1-ahead
    uint4 na0 = ap[0], na1 = ap[32], na2 = ap[64], na3 = ap[96];

    #pragma unroll 2
    for (int ii = 0; ii < CH; ++ii) {
        float4 bJ[4];
        #pragma unroll
        for (int d = 0; d < 4; ++d) bJ[d] = w[d][ii & 1];
        uint4 A0 = na0, A1 = na1, A2 = na2, A3 = na3;

        if (ii + 1 < CH) {
            const int ao = (ii + 1) * 128;
            na0 = ap[ao +  0];
            na1 = ap[ao + 32];
            na2 = ap[ao + 64];
            na3 = ap[ao + 96];
        }
        if (ii + 2 < CH) {
            const size_t wo = (size_t)(ii + 2) * 4096;
            #pragma unroll
            for (int d = 0; d < 4; ++d)
                w[d][ii & 1] = ldcs4(bp + wo + d * 256);
        }

        #pragma unroll
        for (int d = 0; d < 4; ++d) {
            uint32_t b0 = __float_as_uint(bJ[d].x), b1 = __float_as_uint(bJ[d].y);
            uint32_t b2 = __float_as_uint(bJ[d].z), b3 = __float_as_uint(bJ[d].w);
            mma_tf32(c0[d], A0, b0, b1);
            mma_tf32(c1[d], A1, b0, b1);
            mma_tf32(c0[d], A2, b2, b3);
            mma_tf32(c1[d], A3, b2, b3);
        }
    }

    const int brow = lane >> 2;
    const int kc   = kc0 + 2 * (lane & 3);
    const size_t bstr = (size_t)NU_ * US_;
    #pragma unroll
    for (int d = 0; d < 4; ++d) {
        const size_t base = ((size_t)chunk * B_ * NU_ + (j0 + d)) * US_ + kc;
        *(float2*)(g_part + base + (brow     ) * bstr) = make_float2(c0[d][0], c0[d][1]);
        *(float2*)(g_part + base + (brow +  8) * bstr) = make_float2(c0[d][2], c0[d][3]);
        *(float2*)(g_part + base + (brow + 16) * bstr) = make_float2(c1[d][0], c1[d][1]);
        *(float2*)(g_part + base + (brow + 24) * bstr) = make_float2(c1[d][2], c1[d][3]);
    }
}

// ---------------------------------------------------------------------------
// Kernel 3: fused reduce-over-64-chunks + squash + writeout.
// grid (B_, 4 k-quarters) = 128 blocks, block (16 k, 16 j) = 256 threads.
// ---------------------------------------------------------------------------
__global__ void squash_kernel(float* __restrict__ out) {
    __shared__ float vbuf[NU_][17];
    __shared__ float fbuf[16];
    const int b  = blockIdx.x;
    const int kq = blockIdx.y;
    const int kl = threadIdx.x;           // 0..15
    const int j  = threadIdx.y;           // 0..15
    const int k  = kq * 16 + kl;

    const float* __restrict__ p =
        g_part + ((size_t)b * NU_ + j) * US_ + k;
    float s = 0.f;
    #pragma unroll 8
    for (int c = 0; c < ICH; ++c)
        s += p[(size_t)c * (B_ * NU_ * US_)];

    vbuf[j][kl] = s;
    __syncthreads();

    if (j == 0) {
        float msq = 0.f;
        #pragma unroll
        for (int jj = 0; jj < NU_; ++jj) {
            float t = vbuf[jj][kl];
            msq += t * t;
        }
        fbuf[kl] = sqrtf(msq) / (1.0f + msq);
    }
    __syncthreads();

    out[((size_t)b * NU_ + j) * US_ + k] = s * fbuf[kl];
}

// ---------------------------------------------------------------------------
extern "C" void kernel_launch(void* const* d_in, const int* in_sizes, int n_in,
                              void* d_out, int out_size) {
    const float* x = (const float*)d_in[0];
    const float* W = (const float*)d_in[1];
    if (in_sizes[0] != B_ * IU_ * IC_) { const float* t = x; x = W; W = t; }

    prep_kernel<<<dim3(64, 2), 256>>>(x);
    gemm_kernel<<<dim3(ICH, NU_ / 4), 256>>>(W);
    squash_kernel<<<dim3(B_, 4), dim3(16, 16)>>>((float*)d_out);
}